// round 3
// baseline (speedup 1.0000x reference)
#include <cuda_runtime.h>
#include <cstddef>

// Problem constants
#define NN   30000
#define NE   480000
#define DIN  256
#define DREL 128
#define DOUT 512
#define DSUM (DIN + DREL)        // 384
#define DCAT (2 * DIN + DREL)    // 640

// Scratch (device globals: no allocation allowed)
__device__ float g_h2[NN * DIN];       // node_fc(h)            [N, 256]
__device__ float g_hsum[NN * DSUM];    // segment-sum of msgs   [N, 384]
__device__ int   g_deg[NN];            // in-degree per node

__device__ __forceinline__ void red_add_v4(float* addr, float x, float y, float z, float w) {
    asm volatile("red.global.add.v4.f32 [%0], {%1,%2,%3,%4};"
                 :: "l"(addr), "f"(x), "f"(y), "f"(z), "f"(w) : "memory");
}

// ---------------------------------------------------------------------------
// 0) zero h_sum (vectorized) and deg
//    NN*DSUM = 11,520,000 floats = 2,880,000 float4 (exact multiple)
// ---------------------------------------------------------------------------
__global__ void zero_kernel() {
    int i = blockIdx.x * blockDim.x + threadIdx.x;
    if (i < NN * DSUM / 4)
        reinterpret_cast<float4*>(g_hsum)[i] = make_float4(0.f, 0.f, 0.f, 0.f);
    if (i < NN) g_deg[i] = 0;
}

// ---------------------------------------------------------------------------
// 1) in-degree histogram
// ---------------------------------------------------------------------------
__global__ void deg_kernel(const int* __restrict__ dst) {
    int e = blockIdx.x * blockDim.x + threadIdx.x;
    if (e < NE) atomicAdd(&g_deg[dst[e]], 1);
}

// ---------------------------------------------------------------------------
// 2) h2 = h @ Wn + bn    (M=30000, N=256, K=256) -> g_h2
//    128x128x8 tile, 256 threads, 8x8 microtile, double-buffered SMEM
// ---------------------------------------------------------------------------
__global__ __launch_bounds__(256) void node_gemm_kernel(
    const float* __restrict__ A,     // h [NN, DIN]
    const float* __restrict__ B,     // Wn [DIN, DIN]
    const float* __restrict__ bias)  // bn [DIN]
{
    const int BM = 128, BN = 128, BK = 8;
    const int M = NN, N = DIN, K = DIN;
    __shared__ float As[2][BK][BM];
    __shared__ float Bs[2][BK][BN];

    int tid  = threadIdx.x;
    int aRow = tid >> 1;
    int aCol = (tid & 1) << 2;
    int bRow = tid >> 5;
    int bCol = (tid & 31) << 2;
    int rowBase = blockIdx.y * BM;
    int colBase = blockIdx.x * BN;
    int ty = tid >> 4, tx = tid & 15;
    int gr = rowBase + aRow;
    bool aOk = (gr < M);

    float acc[8][8];
#pragma unroll
    for (int i = 0; i < 8; i++)
#pragma unroll
        for (int j = 0; j < 8; j++) acc[i][j] = 0.0f;

    // prologue: load tile 0
    float4 av = make_float4(0.f, 0.f, 0.f, 0.f);
    if (aOk) av = *reinterpret_cast<const float4*>(A + (size_t)gr * K + aCol);
    float4 bv = *reinterpret_cast<const float4*>(B + (size_t)bRow * N + colBase + bCol);
    As[0][aCol + 0][aRow] = av.x;
    As[0][aCol + 1][aRow] = av.y;
    As[0][aCol + 2][aRow] = av.z;
    As[0][aCol + 3][aRow] = av.w;
    *reinterpret_cast<float4*>(&Bs[0][bRow][bCol]) = bv;
    __syncthreads();

    int buf = 0;
    for (int kt = 0; kt < K; kt += BK) {
        bool hasNext = (kt + BK < K);
        if (hasNext) {
            av = make_float4(0.f, 0.f, 0.f, 0.f);
            if (aOk) av = *reinterpret_cast<const float4*>(A + (size_t)gr * K + kt + BK + aCol);
            bv = *reinterpret_cast<const float4*>(B + (size_t)(kt + BK + bRow) * N + colBase + bCol);
        }
#pragma unroll
        for (int k = 0; k < BK; k++) {
            float4 a0 = *reinterpret_cast<const float4*>(&As[buf][k][ty * 8]);
            float4 a1 = *reinterpret_cast<const float4*>(&As[buf][k][ty * 8 + 4]);
            float4 b0 = *reinterpret_cast<const float4*>(&Bs[buf][k][tx * 8]);
            float4 b1 = *reinterpret_cast<const float4*>(&Bs[buf][k][tx * 8 + 4]);
            float ar[8] = {a0.x, a0.y, a0.z, a0.w, a1.x, a1.y, a1.z, a1.w};
            float br[8] = {b0.x, b0.y, b0.z, b0.w, b1.x, b1.y, b1.z, b1.w};
#pragma unroll
            for (int i = 0; i < 8; i++)
#pragma unroll
                for (int j = 0; j < 8; j++)
                    acc[i][j] = fmaf(ar[i], br[j], acc[i][j]);
        }
        if (hasNext) {
            int nb = buf ^ 1;
            As[nb][aCol + 0][aRow] = av.x;
            As[nb][aCol + 1][aRow] = av.y;
            As[nb][aCol + 2][aRow] = av.z;
            As[nb][aCol + 3][aRow] = av.w;
            *reinterpret_cast<float4*>(&Bs[nb][bRow][bCol]) = bv;
            __syncthreads();
            buf = nb;
        }
    }

#pragma unroll
    for (int i = 0; i < 8; i++) {
        int r = rowBase + ty * 8 + i;
        if (r >= M) continue;
#pragma unroll
        for (int j = 0; j < 8; j += 4) {
            int c = colBase + tx * 8 + j;
            float4 o;
            o.x = acc[i][j + 0] + bias[c + 0];
            o.y = acc[i][j + 1] + bias[c + 1];
            o.z = acc[i][j + 2] + bias[c + 2];
            o.w = acc[i][j + 3] + bias[c + 3];
            *reinterpret_cast<float4*>(g_h2 + (size_t)r * N + c) = o;
        }
    }
}

// ---------------------------------------------------------------------------
// 3) z1 src-side: for each edge e: h_sum[dst[e], 0:256] += att[src]*h2[src]
//    64 threads per edge (float4 each), 4 edges per 256-thread block
// ---------------------------------------------------------------------------
__global__ __launch_bounds__(256) void edge_src_kernel(
    const float* __restrict__ natt,
    const int* __restrict__ src,
    const int* __restrict__ dst)
{
    int e    = blockIdx.x * 4 + (threadIdx.x >> 6);
    int lane = threadIdx.x & 63;
    if (e >= NE) return;
    int s = __ldg(&src[e]);
    int d = __ldg(&dst[e]);
    float a = __ldg(&natt[s]);
    float4 v = *reinterpret_cast<const float4*>(g_h2 + (size_t)s * DIN + lane * 4);
    float* p = g_hsum + (size_t)d * DSUM + lane * 4;
    red_add_v4(p, a * v.x, a * v.y, a * v.z, a * v.w);
}

// ---------------------------------------------------------------------------
// 4) z1 dst-side (algebraic): h_sum[d, 0:256] += deg(d)*att[d]*h2[d]
//    (no atomics needed; stream-ordered after edge_src_kernel)
// ---------------------------------------------------------------------------
__global__ __launch_bounds__(64) void node_term_kernel(const float* __restrict__ natt) {
    int n    = blockIdx.x;
    int lane = threadIdx.x;           // 0..63
    float c = (float)g_deg[n] * __ldg(&natt[n]);
    float4 v = *reinterpret_cast<const float4*>(g_h2 + (size_t)n * DIN + lane * 4);
    float* p = g_hsum + (size_t)n * DSUM + lane * 4;
    float4 o = *reinterpret_cast<float4*>(p);
    o.x += c * v.x; o.y += c * v.y; o.z += c * v.z; o.w += c * v.w;
    *reinterpret_cast<float4*>(p) = o;
}

// ---------------------------------------------------------------------------
// 5) z2 fused: tile of (rel @ Wr + br), scaled by edge_att, scattered with
//    red.v4 into h_sum[dst, 256:384].  M=480000 (=3750*128 exact), N=K=128.
//    Double-buffered SMEM.
// ---------------------------------------------------------------------------
__global__ __launch_bounds__(256) void rel_gemm_scatter_kernel(
    const float* __restrict__ A,      // rel [NE, DREL]
    const float* __restrict__ B,      // Wr [DREL, DREL]
    const float* __restrict__ bias,   // br [DREL]
    const float* __restrict__ eatt,   // [NE]
    const int* __restrict__ dst)
{
    const int BM = 128, BN = 128, BK = 8;
    const int N = DREL, K = DREL;
    __shared__ float As[2][BK][BM];
    __shared__ float Bs[2][BK][BN];

    int tid  = threadIdx.x;
    int aRow = tid >> 1;
    int aCol = (tid & 1) << 2;
    int bRow = tid >> 5;
    int bCol = (tid & 31) << 2;
    int rowBase = blockIdx.y * BM;    // always in bounds (480000 % 128 == 0)
    int ty = tid >> 4, tx = tid & 15;
    int gr = rowBase + aRow;

    float acc[8][8];
#pragma unroll
    for (int i = 0; i < 8; i++)
#pragma unroll
        for (int j = 0; j < 8; j++) acc[i][j] = 0.0f;

    float4 av = *reinterpret_cast<const float4*>(A + (size_t)gr * K + aCol);
    float4 bv = *reinterpret_cast<const float4*>(B + (size_t)bRow * N + bCol);
    As[0][aCol + 0][aRow] = av.x;
    As[0][aCol + 1][aRow] = av.y;
    As[0][aCol + 2][aRow] = av.z;
    As[0][aCol + 3][aRow] = av.w;
    *reinterpret_cast<float4*>(&Bs[0][bRow][bCol]) = bv;
    __syncthreads();

    int buf = 0;
    for (int kt = 0; kt < K; kt += BK) {
        bool hasNext = (kt + BK < K);
        if (hasNext) {
            av = *reinterpret_cast<const float4*>(A + (size_t)gr * K + kt + BK + aCol);
            bv = *reinterpret_cast<const float4*>(B + (size_t)(kt + BK + bRow) * N + bCol);
        }
#pragma unroll
        for (int k = 0; k < BK; k++) {
            float4 a0 = *reinterpret_cast<const float4*>(&As[buf][k][ty * 8]);
            float4 a1 = *reinterpret_cast<const float4*>(&As[buf][k][ty * 8 + 4]);
            float4 b0 = *reinterpret_cast<const float4*>(&Bs[buf][k][tx * 8]);
            float4 b1 = *reinterpret_cast<const float4*>(&Bs[buf][k][tx * 8 + 4]);
            float ar[8] = {a0.x, a0.y, a0.z, a0.w, a1.x, a1.y, a1.z, a1.w};
            float br[8] = {b0.x, b0.y, b0.z, b0.w, b1.x, b1.y, b1.z, b1.w};
#pragma unroll
            for (int i = 0; i < 8; i++)
#pragma unroll
                for (int j = 0; j < 8; j++)
                    acc[i][j] = fmaf(ar[i], br[j], acc[i][j]);
        }
        if (hasNext) {
            int nb = buf ^ 1;
            As[nb][aCol + 0][aRow] = av.x;
            As[nb][aCol + 1][aRow] = av.y;
            As[nb][aCol + 2][aRow] = av.z;
            As[nb][aCol + 3][aRow] = av.w;
            *reinterpret_cast<float4*>(&Bs[nb][bRow][bCol]) = bv;
            __syncthreads();
            buf = nb;
        }
    }

    // epilogue: z2[r, c] = eatt[r] * (acc + br[c]); scatter to h_sum[dst[r], 256+c]
#pragma unroll
    for (int i = 0; i < 8; i++) {
        int r = rowBase + ty * 8 + i;
        float s = __ldg(&eatt[r]);
        int d   = __ldg(&dst[r]);
        float* base = g_hsum + (size_t)d * DSUM + DIN + tx * 8;
#pragma unroll
        for (int j = 0; j < 8; j += 4) {
            int c = tx * 8 + j;
            red_add_v4(base + j,
                       s * (acc[i][j + 0] + bias[c + 0]),
                       s * (acc[i][j + 1] + bias[c + 1]),
                       s * (acc[i][j + 2] + bias[c + 2]),
                       s * (acc[i][j + 3] + bias[c + 3]));
        }
    }
}

// ---------------------------------------------------------------------------
// 6) out = relu([h2 | h_sum] @ Wa + ba)   M=30000, N=512, K=640
//    A is the virtual concat: k<256 -> g_h2, else g_hsum. Double-buffered.
// ---------------------------------------------------------------------------
__global__ __launch_bounds__(256) void final_gemm_kernel(
    const float* __restrict__ B,      // Wa [DCAT, DOUT]
    const float* __restrict__ bias,   // ba [DOUT]
    float* __restrict__ C)            // out [NN, DOUT]
{
    const int BM = 128, BN = 128, BK = 8;
    const int M = NN, N = DOUT, K = DCAT;
    __shared__ float As[2][BK][BM];
    __shared__ float Bs[2][BK][BN];

    int tid  = threadIdx.x;
    int aRow = tid >> 1;
    int aCol = (tid & 1) << 2;
    int bRow = tid >> 5;
    int bCol = (tid & 31) << 2;
    int rowBase = blockIdx.y * BM;
    int colBase = blockIdx.x * BN;
    int ty = tid >> 4, tx = tid & 15;
    int gr = rowBase + aRow;
    bool aOk = (gr < M);

    float acc[8][8];
#pragma unroll
    for (int i = 0; i < 8; i++)
#pragma unroll
        for (int j = 0; j < 8; j++) acc[i][j] = 0.0f;

    auto loadA = [&](int kk) -> float4 {
        if (!aOk) return make_float4(0.f, 0.f, 0.f, 0.f);
        const float* ap = (kk < DIN)
            ? (g_h2   + (size_t)gr * DIN  + kk)
            : (g_hsum + (size_t)gr * DSUM + (kk - DIN));
        return *reinterpret_cast<const float4*>(ap);
    };

    float4 av = loadA(aCol);
    float4 bv = *reinterpret_cast<const float4*>(B + (size_t)bRow * N + colBase + bCol);
    As[0][aCol + 0][aRow] = av.x;
    As[0][aCol + 1][aRow] = av.y;
    As[0][aCol + 2][aRow] = av.z;
    As[0][aCol + 3][aRow] = av.w;
    *reinterpret_cast<float4*>(&Bs[0][bRow][bCol]) = bv;
    __syncthreads();

    int buf = 0;
    for (int kt = 0; kt < K; kt += BK) {
        bool hasNext = (kt + BK < K);
        if (hasNext) {
            av = loadA(kt + BK + aCol);
            bv = *reinterpret_cast<const float4*>(B + (size_t)(kt + BK + bRow) * N + colBase + bCol);
        }
#pragma unroll
        for (int k = 0; k < BK; k++) {
            float4 a0 = *reinterpret_cast<const float4*>(&As[buf][k][ty * 8]);
            float4 a1 = *reinterpret_cast<const float4*>(&As[buf][k][ty * 8 + 4]);
            float4 b0 = *reinterpret_cast<const float4*>(&Bs[buf][k][tx * 8]);
            float4 b1 = *reinterpret_cast<const float4*>(&Bs[buf][k][tx * 8 + 4]);
            float ar[8] = {a0.x, a0.y, a0.z, a0.w, a1.x, a1.y, a1.z, a1.w};
            float br[8] = {b0.x, b0.y, b0.z, b0.w, b1.x, b1.y, b1.z, b1.w};
#pragma unroll
            for (int i = 0; i < 8; i++)
#pragma unroll
                for (int j = 0; j < 8; j++)
                    acc[i][j] = fmaf(ar[i], br[j], acc[i][j]);
        }
        if (hasNext) {
            int nb = buf ^ 1;
            As[nb][aCol + 0][aRow] = av.x;
            As[nb][aCol + 1][aRow] = av.y;
            As[nb][aCol + 2][aRow] = av.z;
            As[nb][aCol + 3][aRow] = av.w;
            *reinterpret_cast<float4*>(&Bs[nb][bRow][bCol]) = bv;
            __syncthreads();
            buf = nb;
        }
    }

#pragma unroll
    for (int i = 0; i < 8; i++) {
        int r = rowBase + ty * 8 + i;
        if (r >= M) continue;
#pragma unroll
        for (int j = 0; j < 8; j += 4) {
            int c = colBase + tx * 8 + j;
            float4 o;
            o.x = fmaxf(acc[i][j + 0] + bias[c + 0], 0.f);
            o.y = fmaxf(acc[i][j + 1] + bias[c + 1], 0.f);
            o.z = fmaxf(acc[i][j + 2] + bias[c + 2], 0.f);
            o.w = fmaxf(acc[i][j + 3] + bias[c + 3], 0.f);
            *reinterpret_cast<float4*>(C + (size_t)r * N + c) = o;
        }
    }
}

// ---------------------------------------------------------------------------
extern "C" void kernel_launch(void* const* d_in, const int* in_sizes, int n_in,
                              void* d_out, int out_size) {
    const float* h    = (const float*)d_in[0];
    const float* natt = (const float*)d_in[1];
    const float* rel  = (const float*)d_in[2];
    const float* eatt = (const float*)d_in[3];
    const float* Wn   = (const float*)d_in[4];
    const float* bn   = (const float*)d_in[5];
    const float* Wr   = (const float*)d_in[6];
    const float* br   = (const float*)d_in[7];
    const float* Wa   = (const float*)d_in[8];
    const float* ba   = (const float*)d_in[9];
    const int*   src  = (const int*)d_in[10];
    const int*   dst  = (const int*)d_in[11];
    float* out = (float*)d_out;
    (void)in_sizes; (void)n_in; (void)out_size;

    // 0) zero scratch (float4-vectorized)
    zero_kernel<<<(NN * DSUM / 4 + 255) / 256, 256>>>();
    // 1) in-degree histogram
    deg_kernel<<<(NE + 255) / 256, 256>>>(dst);
    // 2) h2 = h@Wn + bn
    {
        dim3 g(DIN / 128, (NN + 127) / 128);
        node_gemm_kernel<<<g, 256>>>(h, Wn, bn);
    }
    // 3) src-side message scatter
    edge_src_kernel<<<NE / 4, 256>>>(natt, src, dst);
    // 4) dst-side term (deg-weighted, non-atomic)
    node_term_kernel<<<NN, 64>>>(natt);
    // 5) rel GEMM fused with scatter into h_sum[:, 256:384]
    {
        dim3 g(1, NE / 128);
        rel_gemm_scatter_kernel<<<g, 256>>>(rel, Wr, br, eatt, dst);
    }
    // 6) final GEMM + bias + relu
    {
        dim3 g(DOUT / 128, (NN + 127) / 128);
        final_gemm_kernel<<<g, 256>>>(Wa, ba, out);
    }
}

// round 4
// speedup vs baseline: 1.0287x; 1.0287x over previous
#include <cuda_runtime.h>
#include <cstddef>

// Problem constants
#define NN   30000
#define NE   480000
#define DIN  256
#define DREL 128
#define DOUT 512
#define DSUM (DIN + DREL)        // 384
#define DCAT (2 * DIN + DREL)    // 640

// Scratch (device globals: no allocation allowed)
__device__ float g_h2[NN * DIN];       // node_fc(h)            [N, 256]
__device__ float g_hsum[NN * DSUM];    // segment-sum of msgs   [N, 384]
__device__ int   g_deg[NN];            // in-degree per node

__device__ __forceinline__ void red_add_v4(float* addr, float x, float y, float z, float w) {
    asm volatile("red.global.add.v4.f32 [%0], {%1,%2,%3,%4};"
                 :: "l"(addr), "f"(x), "f"(y), "f"(z), "f"(w) : "memory");
}

// ---- packed f32x2 helpers (sm_103a) ---------------------------------------
__device__ __forceinline__ unsigned long long bcast2(float x) {
    unsigned long long r;
    unsigned xu = __float_as_uint(x);
    asm("mov.b64 %0, {%1, %1};" : "=l"(r) : "r"(xu));
    return r;
}
__device__ __forceinline__ void fma2(unsigned long long& acc,
                                     unsigned long long a, unsigned long long b) {
    asm("fma.rn.f32x2 %0, %1, %2, %0;" : "+l"(acc) : "l"(a), "l"(b));
}
__device__ __forceinline__ float lo2(unsigned long long v) {
    return __uint_as_float((unsigned)(v & 0xffffffffull));
}
__device__ __forceinline__ float hi2(unsigned long long v) {
    return __uint_as_float((unsigned)(v >> 32));
}

// ---------------------------------------------------------------------------
// 0) zero h_sum (vectorized) and deg
// ---------------------------------------------------------------------------
__global__ void zero_kernel() {
    int i = blockIdx.x * blockDim.x + threadIdx.x;
    if (i < NN * DSUM / 4)
        reinterpret_cast<float4*>(g_hsum)[i] = make_float4(0.f, 0.f, 0.f, 0.f);
    if (i < NN) g_deg[i] = 0;
}

// ---------------------------------------------------------------------------
// 1) in-degree histogram
// ---------------------------------------------------------------------------
__global__ void deg_kernel(const int* __restrict__ dst) {
    int e = blockIdx.x * blockDim.x + threadIdx.x;
    if (e < NE) atomicAdd(&g_deg[dst[e]], 1);
}

// ---------------------------------------------------------------------------
// shared inner product: acc2[8][4] += broadcast(A-col) * B-pairs, one k-step.
// As row: 8 floats (microtile i), Bs row: 8 floats = 4 packed pairs (j).
// ---------------------------------------------------------------------------
#define MICRO_K_STEP(ASROW, BSROW)                                             \
    do {                                                                       \
        float4 _a0 = *reinterpret_cast<const float4*>(ASROW);                  \
        float4 _a1 = *reinterpret_cast<const float4*>((ASROW) + 4);            \
        const unsigned long long* _bp =                                        \
            reinterpret_cast<const unsigned long long*>(BSROW);                \
        unsigned long long _b0 = _bp[0], _b1 = _bp[1],                         \
                           _b2 = _bp[2], _b3 = _bp[3];                         \
        unsigned long long _ab;                                                \
        _ab = bcast2(_a0.x);                                                   \
        fma2(acc2[0][0], _ab, _b0); fma2(acc2[0][1], _ab, _b1);                \
        fma2(acc2[0][2], _ab, _b2); fma2(acc2[0][3], _ab, _b3);                \
        _ab = bcast2(_a0.y);                                                   \
        fma2(acc2[1][0], _ab, _b0); fma2(acc2[1][1], _ab, _b1);                \
        fma2(acc2[1][2], _ab, _b2); fma2(acc2[1][3], _ab, _b3);                \
        _ab = bcast2(_a0.z);                                                   \
        fma2(acc2[2][0], _ab, _b0); fma2(acc2[2][1], _ab, _b1);                \
        fma2(acc2[2][2], _ab, _b2); fma2(acc2[2][3], _ab, _b3);                \
        _ab = bcast2(_a0.w);                                                   \
        fma2(acc2[3][0], _ab, _b0); fma2(acc2[3][1], _ab, _b1);                \
        fma2(acc2[3][2], _ab, _b2); fma2(acc2[3][3], _ab, _b3);                \
        _ab = bcast2(_a1.x);                                                   \
        fma2(acc2[4][0], _ab, _b0); fma2(acc2[4][1], _ab, _b1);                \
        fma2(acc2[4][2], _ab, _b2); fma2(acc2[4][3], _ab, _b3);                \
        _ab = bcast2(_a1.y);                                                   \
        fma2(acc2[5][0], _ab, _b0); fma2(acc2[5][1], _ab, _b1);                \
        fma2(acc2[5][2], _ab, _b2); fma2(acc2[5][3], _ab, _b3);                \
        _ab = bcast2(_a1.z);                                                   \
        fma2(acc2[6][0], _ab, _b0); fma2(acc2[6][1], _ab, _b1);                \
        fma2(acc2[6][2], _ab, _b2); fma2(acc2[6][3], _ab, _b3);                \
        _ab = bcast2(_a1.w);                                                   \
        fma2(acc2[7][0], _ab, _b0); fma2(acc2[7][1], _ab, _b1);                \
        fma2(acc2[7][2], _ab, _b2); fma2(acc2[7][3], _ab, _b3);                \
    } while (0)

// ---------------------------------------------------------------------------
// 2) h2 = h @ Wn + bn    (M=30000, N=256, K=256) -> g_h2
// ---------------------------------------------------------------------------
__global__ __launch_bounds__(256) void node_gemm_kernel(
    const float* __restrict__ A,     // h [NN, DIN]
    const float* __restrict__ B,     // Wn [DIN, DIN]
    const float* __restrict__ bias)  // bn [DIN]
{
    const int BM = 128, BN = 128, BK = 8;
    const int M = NN, N = DIN, K = DIN;
    __shared__ float As[2][BK][BM];
    __shared__ float Bs[2][BK][BN];

    int tid  = threadIdx.x;
    int aRow = tid >> 1;
    int aCol = (tid & 1) << 2;
    int bRow = tid >> 5;
    int bCol = (tid & 31) << 2;
    int rowBase = blockIdx.y * BM;
    int colBase = blockIdx.x * BN;
    int ty = tid >> 4, tx = tid & 15;
    int gr = rowBase + aRow;
    bool aOk = (gr < M);

    unsigned long long acc2[8][4];
#pragma unroll
    for (int i = 0; i < 8; i++)
#pragma unroll
        for (int j = 0; j < 4; j++) acc2[i][j] = 0ull;

    float4 av = make_float4(0.f, 0.f, 0.f, 0.f);
    if (aOk) av = *reinterpret_cast<const float4*>(A + (size_t)gr * K + aCol);
    float4 bv = *reinterpret_cast<const float4*>(B + (size_t)bRow * N + colBase + bCol);
    As[0][aCol + 0][aRow] = av.x;
    As[0][aCol + 1][aRow] = av.y;
    As[0][aCol + 2][aRow] = av.z;
    As[0][aCol + 3][aRow] = av.w;
    *reinterpret_cast<float4*>(&Bs[0][bRow][bCol]) = bv;
    __syncthreads();

    int buf = 0;
    for (int kt = 0; kt < K; kt += BK) {
        bool hasNext = (kt + BK < K);
        if (hasNext) {
            av = make_float4(0.f, 0.f, 0.f, 0.f);
            if (aOk) av = *reinterpret_cast<const float4*>(A + (size_t)gr * K + kt + BK + aCol);
            bv = *reinterpret_cast<const float4*>(B + (size_t)(kt + BK + bRow) * N + colBase + bCol);
        }
#pragma unroll
        for (int k = 0; k < BK; k++)
            MICRO_K_STEP(&As[buf][k][ty * 8], &Bs[buf][k][tx * 8]);
        if (hasNext) {
            int nb = buf ^ 1;
            As[nb][aCol + 0][aRow] = av.x;
            As[nb][aCol + 1][aRow] = av.y;
            As[nb][aCol + 2][aRow] = av.z;
            As[nb][aCol + 3][aRow] = av.w;
            *reinterpret_cast<float4*>(&Bs[nb][bRow][bCol]) = bv;
            __syncthreads();
            buf = nb;
        }
    }

#pragma unroll
    for (int i = 0; i < 8; i++) {
        int r = rowBase + ty * 8 + i;
        if (r >= M) continue;
#pragma unroll
        for (int jp = 0; jp < 4; jp += 2) {
            int c = colBase + tx * 8 + jp * 2;
            float4 o;
            o.x = lo2(acc2[i][jp + 0]) + bias[c + 0];
            o.y = hi2(acc2[i][jp + 0]) + bias[c + 1];
            o.z = lo2(acc2[i][jp + 1]) + bias[c + 2];
            o.w = hi2(acc2[i][jp + 1]) + bias[c + 3];
            *reinterpret_cast<float4*>(g_h2 + (size_t)r * N + c) = o;
        }
    }
}

// ---------------------------------------------------------------------------
// 3) z1 src-side: h_sum[dst[e], 0:256] += att[src]*h2[src]
// ---------------------------------------------------------------------------
__global__ __launch_bounds__(256) void edge_src_kernel(
    const float* __restrict__ natt,
    const int* __restrict__ src,
    const int* __restrict__ dst)
{
    int e    = blockIdx.x * 4 + (threadIdx.x >> 6);
    int lane = threadIdx.x & 63;
    if (e >= NE) return;
    int s = __ldg(&src[e]);
    int d = __ldg(&dst[e]);
    float a = __ldg(&natt[s]);
    float4 v = *reinterpret_cast<const float4*>(g_h2 + (size_t)s * DIN + lane * 4);
    float* p = g_hsum + (size_t)d * DSUM + lane * 4;
    red_add_v4(p, a * v.x, a * v.y, a * v.z, a * v.w);
}

// ---------------------------------------------------------------------------
// 4) z1 dst-side (algebraic): h_sum[d, 0:256] += deg(d)*att[d]*h2[d]
// ---------------------------------------------------------------------------
__global__ __launch_bounds__(64) void node_term_kernel(const float* __restrict__ natt) {
    int n    = blockIdx.x;
    int lane = threadIdx.x;           // 0..63
    float c = (float)g_deg[n] * __ldg(&natt[n]);
    float4 v = *reinterpret_cast<const float4*>(g_h2 + (size_t)n * DIN + lane * 4);
    float* p = g_hsum + (size_t)n * DSUM + lane * 4;
    float4 o = *reinterpret_cast<float4*>(p);
    o.x += c * v.x; o.y += c * v.y; o.z += c * v.z; o.w += c * v.w;
    *reinterpret_cast<float4*>(p) = o;
}

// ---------------------------------------------------------------------------
// 5) z2 fused: (rel @ Wr + br) * eatt scattered into h_sum[dst, 256:384]
// ---------------------------------------------------------------------------
__global__ __launch_bounds__(256) void rel_gemm_scatter_kernel(
    const float* __restrict__ A,      // rel [NE, DREL]
    const float* __restrict__ B,      // Wr [DREL, DREL]
    const float* __restrict__ bias,   // br [DREL]
    const float* __restrict__ eatt,   // [NE]
    const int* __restrict__ dst)
{
    const int BM = 128, BN = 128, BK = 8;
    const int N = DREL, K = DREL;
    __shared__ float As[2][BK][BM];
    __shared__ float Bs[2][BK][BN];

    int tid  = threadIdx.x;
    int aRow = tid >> 1;
    int aCol = (tid & 1) << 2;
    int bRow = tid >> 5;
    int bCol = (tid & 31) << 2;
    int rowBase = blockIdx.y * BM;    // always in bounds (480000 % 128 == 0)
    int ty = tid >> 4, tx = tid & 15;
    int gr = rowBase + aRow;

    unsigned long long acc2[8][4];
#pragma unroll
    for (int i = 0; i < 8; i++)
#pragma unroll
        for (int j = 0; j < 4; j++) acc2[i][j] = 0ull;

    float4 av = *reinterpret_cast<const float4*>(A + (size_t)gr * K + aCol);
    float4 bv = *reinterpret_cast<const float4*>(B + (size_t)bRow * N + bCol);
    As[0][aCol + 0][aRow] = av.x;
    As[0][aCol + 1][aRow] = av.y;
    As[0][aCol + 2][aRow] = av.z;
    As[0][aCol + 3][aRow] = av.w;
    *reinterpret_cast<float4*>(&Bs[0][bRow][bCol]) = bv;
    __syncthreads();

    int buf = 0;
    for (int kt = 0; kt < K; kt += BK) {
        bool hasNext = (kt + BK < K);
        if (hasNext) {
            av = *reinterpret_cast<const float4*>(A + (size_t)gr * K + kt + BK + aCol);
            bv = *reinterpret_cast<const float4*>(B + (size_t)(kt + BK + bRow) * N + bCol);
        }
#pragma unroll
        for (int k = 0; k < BK; k++)
            MICRO_K_STEP(&As[buf][k][ty * 8], &Bs[buf][k][tx * 8]);
        if (hasNext) {
            int nb = buf ^ 1;
            As[nb][aCol + 0][aRow] = av.x;
            As[nb][aCol + 1][aRow] = av.y;
            As[nb][aCol + 2][aRow] = av.z;
            As[nb][aCol + 3][aRow] = av.w;
            *reinterpret_cast<float4*>(&Bs[nb][bRow][bCol]) = bv;
            __syncthreads();
            buf = nb;
        }
    }

    // epilogue: z2[r, c] = eatt[r] * (acc + br[c]); scatter to h_sum[dst[r], 256+c]
#pragma unroll
    for (int i = 0; i < 8; i++) {
        int r = rowBase + ty * 8 + i;
        float s = __ldg(&eatt[r]);
        int d   = __ldg(&dst[r]);
        float* base = g_hsum + (size_t)d * DSUM + DIN + tx * 8;
#pragma unroll
        for (int jp = 0; jp < 4; jp += 2) {
            int c = tx * 8 + jp * 2;
            red_add_v4(base + jp * 2,
                       s * (lo2(acc2[i][jp + 0]) + bias[c + 0]),
                       s * (hi2(acc2[i][jp + 0]) + bias[c + 1]),
                       s * (lo2(acc2[i][jp + 1]) + bias[c + 2]),
                       s * (hi2(acc2[i][jp + 1]) + bias[c + 3]));
        }
    }
}

// ---------------------------------------------------------------------------
// 6) out = relu([h2 | h_sum] @ Wa + ba)   M=30000, N=512, K=640
// ---------------------------------------------------------------------------
__global__ __launch_bounds__(256) void final_gemm_kernel(
    const float* __restrict__ B,      // Wa [DCAT, DOUT]
    const float* __restrict__ bias,   // ba [DOUT]
    float* __restrict__ C)            // out [NN, DOUT]
{
    const int BM = 128, BN = 128, BK = 8;
    const int M = NN, N = DOUT, K = DCAT;
    __shared__ float As[2][BK][BM];
    __shared__ float Bs[2][BK][BN];

    int tid  = threadIdx.x;
    int aRow = tid >> 1;
    int aCol = (tid & 1) << 2;
    int bRow = tid >> 5;
    int bCol = (tid & 31) << 2;
    int rowBase = blockIdx.y * BM;
    int colBase = blockIdx.x * BN;
    int ty = tid >> 4, tx = tid & 15;
    int gr = rowBase + aRow;
    bool aOk = (gr < M);

    unsigned long long acc2[8][4];
#pragma unroll
    for (int i = 0; i < 8; i++)
#pragma unroll
        for (int j = 0; j < 4; j++) acc2[i][j] = 0ull;

    auto loadA = [&](int kk) -> float4 {
        if (!aOk) return make_float4(0.f, 0.f, 0.f, 0.f);
        const float* ap = (kk < DIN)
            ? (g_h2   + (size_t)gr * DIN  + kk)
            : (g_hsum + (size_t)gr * DSUM + (kk - DIN));
        return *reinterpret_cast<const float4*>(ap);
    };

    float4 av = loadA(aCol);
    float4 bv = *reinterpret_cast<const float4*>(B + (size_t)bRow * N + colBase + bCol);
    As[0][aCol + 0][aRow] = av.x;
    As[0][aCol + 1][aRow] = av.y;
    As[0][aCol + 2][aRow] = av.z;
    As[0][aCol + 3][aRow] = av.w;
    *reinterpret_cast<float4*>(&Bs[0][bRow][bCol]) = bv;
    __syncthreads();

    int buf = 0;
    for (int kt = 0; kt < K; kt += BK) {
        bool hasNext = (kt + BK < K);
        if (hasNext) {
            av = loadA(kt + BK + aCol);
            bv = *reinterpret_cast<const float4*>(B + (size_t)(kt + BK + bRow) * N + colBase + bCol);
        }
#pragma unroll
        for (int k = 0; k < BK; k++)
            MICRO_K_STEP(&As[buf][k][ty * 8], &Bs[buf][k][tx * 8]);
        if (hasNext) {
            int nb = buf ^ 1;
            As[nb][aCol + 0][aRow] = av.x;
            As[nb][aCol + 1][aRow] = av.y;
            As[nb][aCol + 2][aRow] = av.z;
            As[nb][aCol + 3][aRow] = av.w;
            *reinterpret_cast<float4*>(&Bs[nb][bRow][bCol]) = bv;
            __syncthreads();
            buf = nb;
        }
    }

#pragma unroll
    for (int i = 0; i < 8; i++) {
        int r = rowBase + ty * 8 + i;
        if (r >= M) continue;
#pragma unroll
        for (int jp = 0; jp < 4; jp += 2) {
            int c = colBase + tx * 8 + jp * 2;
            float4 o;
            o.x = fmaxf(lo2(acc2[i][jp + 0]) + bias[c + 0], 0.f);
            o.y = fmaxf(hi2(acc2[i][jp + 0]) + bias[c + 1], 0.f);
            o.z = fmaxf(lo2(acc2[i][jp + 1]) + bias[c + 2], 0.f);
            o.w = fmaxf(hi2(acc2[i][jp + 1]) + bias[c + 3], 0.f);
            *reinterpret_cast<float4*>(C + (size_t)r * N + c) = o;
        }
    }
}

// ---------------------------------------------------------------------------
extern "C" void kernel_launch(void* const* d_in, const int* in_sizes, int n_in,
                              void* d_out, int out_size) {
    const float* h    = (const float*)d_in[0];
    const float* natt = (const float*)d_in[1];
    const float* rel  = (const float*)d_in[2];
    const float* eatt = (const float*)d_in[3];
    const float* Wn   = (const float*)d_in[4];
    const float* bn   = (const float*)d_in[5];
    const float* Wr   = (const float*)d_in[6];
    const float* br   = (const float*)d_in[7];
    const float* Wa   = (const float*)d_in[8];
    const float* ba   = (const float*)d_in[9];
    const int*   src  = (const int*)d_in[10];
    const int*   dst  = (const int*)d_in[11];
    float* out = (float*)d_out;
    (void)in_sizes; (void)n_in; (void)out_size;

    // 0) zero scratch (float4-vectorized)
    zero_kernel<<<(NN * DSUM / 4 + 255) / 256, 256>>>();
    // 1) in-degree histogram
    deg_kernel<<<(NE + 255) / 256, 256>>>(dst);
    // 2) h2 = h@Wn + bn
    {
        dim3 g(DIN / 128, (NN + 127) / 128);
        node_gemm_kernel<<<g, 256>>>(h, Wn, bn);
    }
    // 3) src-side message scatter
    edge_src_kernel<<<NE / 4, 256>>>(natt, src, dst);
    // 4) dst-side term (deg-weighted, non-atomic)
    node_term_kernel<<<NN, 64>>>(natt);
    // 5) rel GEMM fused with scatter into h_sum[:, 256:384]
    {
        dim3 g(1, NE / 128);
        rel_gemm_scatter_kernel<<<g, 256>>>(rel, Wr, br, eatt, dst);
    }
    // 6) final GEMM + bias + relu
    {
        dim3 g(DOUT / 128, (NN + 127) / 128);
        final_gemm_kernel<<<g, 256>>>(Wa, ba, out);
    }
}

// round 10
// speedup vs baseline: 1.5924x; 1.5480x over previous
#include <cuda_runtime.h>
#include <cuda_bf16.h>
#include <cstddef>
#include <cstdint>

// Problem constants
#define NN   30000
#define NE   480000
#define DIN  256
#define DREL 128
#define DOUT 512
#define DSUM (DIN + DREL)        // 384
#define DCAT (2 * DIN + DREL)    // 640

// Scratch (device globals: no allocation allowed; 16B-aligned)
__device__ __align__(16) float g_h2[NN * DIN];
__device__ __align__(16) float g_hsum[NN * DSUM];
__device__ int   g_deg[NN];
__device__ __align__(16) __nv_bfloat16 g_wt_hi[DOUT * DCAT];  // Wa^T hi [n][k]
__device__ __align__(16) __nv_bfloat16 g_wt_lo[DOUT * DCAT];  // Wa^T lo [n][k]
__device__ __align__(16) __nv_bfloat16 g_wr_hi[DREL * DREL];  // Wr^T hi [n][k]
__device__ __align__(16) __nv_bfloat16 g_wr_lo[DREL * DREL];  // Wr^T lo [n][k]

__device__ __forceinline__ void red_add_v4(float* addr, float x, float y, float z, float w) {
    asm volatile("red.global.add.v4.f32 [%0], {%1,%2,%3,%4};"
                 :: "l"(addr), "f"(x), "f"(y), "f"(z), "f"(w) : "memory");
}
__device__ __forceinline__ void red_add_v2(float* addr, float x, float y) {
    asm volatile("red.global.add.v2.f32 [%0], {%1,%2};"
                 :: "l"(addr), "f"(x), "f"(y) : "memory");
}

// ---- packed f32x2 helpers ------------------------------------------------
__device__ __forceinline__ unsigned long long bcast2(float x) {
    unsigned long long r;
    unsigned xu = __float_as_uint(x);
    asm("mov.b64 %0, {%1, %1};" : "=l"(r) : "r"(xu));
    return r;
}
__device__ __forceinline__ void fma2(unsigned long long& acc,
                                     unsigned long long a, unsigned long long b) {
    asm("fma.rn.f32x2 %0, %1, %2, %0;" : "+l"(acc) : "l"(a), "l"(b));
}
__device__ __forceinline__ float lo2(unsigned long long v) {
    return __uint_as_float((unsigned)(v & 0xffffffffull));
}
__device__ __forceinline__ float hi2(unsigned long long v) {
    return __uint_as_float((unsigned)(v >> 32));
}

// ---- bf16 split helpers ---------------------------------------------------
__device__ __forceinline__ unsigned pack_bf16x2(__nv_bfloat16 a, __nv_bfloat16 b) {
    unsigned short au = __bfloat16_as_ushort(a), bu = __bfloat16_as_ushort(b);
    return (unsigned)au | ((unsigned)bu << 16);
}
__device__ __forceinline__ void split_bf16(float x, __nv_bfloat16& h, __nv_bfloat16& l) {
    h = __float2bfloat16_rn(x);
    l = __float2bfloat16_rn(x - __bfloat162float(h));
}

// ---- warp-level bf16 mma (baseline PTX, sm_80+) ---------------------------
__device__ __forceinline__ void mma_bf16(float c[4], const unsigned a[4], const unsigned b[2]) {
    asm volatile("mma.sync.aligned.m16n8k16.row.col.f32.bf16.bf16.f32 "
                 "{%0,%1,%2,%3}, {%4,%5,%6,%7}, {%8,%9}, {%0,%1,%2,%3};"
                 : "+f"(c[0]), "+f"(c[1]), "+f"(c[2]), "+f"(c[3])
                 : "r"(a[0]), "r"(a[1]), "r"(a[2]), "r"(a[3]), "r"(b[0]), "r"(b[1]));
}

// ---------------------------------------------------------------------------
// 0) zero h_sum (vectorized) and deg
// ---------------------------------------------------------------------------
__global__ void zero_kernel() {
    int i = blockIdx.x * blockDim.x + threadIdx.x;
    if (i < NN * DSUM / 4)
        reinterpret_cast<float4*>(g_hsum)[i] = make_float4(0.f, 0.f, 0.f, 0.f);
    if (i < NN) g_deg[i] = 0;
}

// ---------------------------------------------------------------------------
// 1) in-degree histogram
// ---------------------------------------------------------------------------
__global__ void deg_kernel(const int* __restrict__ dst) {
    int e = blockIdx.x * blockDim.x + threadIdx.x;
    if (e < NE) atomicAdd(&g_deg[dst[e]], 1);
}

// ---------------------------------------------------------------------------
// 1b) transpose + bf16-split Wa: g_wt_{hi,lo}[n*DCAT + k] = split(Wa[k,n])
// ---------------------------------------------------------------------------
__global__ void prep_w_kernel(const float* __restrict__ Wa) {
    int i = blockIdx.x * blockDim.x + threadIdx.x;
    if (i >= DOUT * DCAT) return;
    int n = i / DCAT, k = i % DCAT;
    float x = Wa[(size_t)k * DOUT + n];
    __nv_bfloat16 h, l;
    split_bf16(x, h, l);
    g_wt_hi[i] = h;
    g_wt_lo[i] = l;
}

// 1c) transpose + bf16-split Wr: g_wr_{hi,lo}[n*DREL + k] = split(Wr[k,n])
__global__ void prep_wr_kernel(const float* __restrict__ Wr) {
    int i = blockIdx.x * blockDim.x + threadIdx.x;
    if (i >= DREL * DREL) return;
    int n = i / DREL, k = i % DREL;
    float x = Wr[(size_t)k * DREL + n];
    __nv_bfloat16 h, l;
    split_bf16(x, h, l);
    g_wr_hi[i] = h;
    g_wr_lo[i] = l;
}

// ---------------------------------------------------------------------------
// shared FFMA2 microkernel (R4, proven) — used by node GEMM only now
// ---------------------------------------------------------------------------
#define MICRO_K_STEP(ASROW, BSROW)                                             \
    do {                                                                       \
        float4 _a0 = *reinterpret_cast<const float4*>(ASROW);                  \
        float4 _a1 = *reinterpret_cast<const float4*>((ASROW) + 4);            \
        const unsigned long long* _bp =                                        \
            reinterpret_cast<const unsigned long long*>(BSROW);                \
        unsigned long long _b0 = _bp[0], _b1 = _bp[1],                         \
                           _b2 = _bp[2], _b3 = _bp[3];                         \
        unsigned long long _ab;                                                \
        _ab = bcast2(_a0.x);                                                   \
        fma2(acc2[0][0], _ab, _b0); fma2(acc2[0][1], _ab, _b1);                \
        fma2(acc2[0][2], _ab, _b2); fma2(acc2[0][3], _ab, _b3);                \
        _ab = bcast2(_a0.y);                                                   \
        fma2(acc2[1][0], _ab, _b0); fma2(acc2[1][1], _ab, _b1);                \
        fma2(acc2[1][2], _ab, _b2); fma2(acc2[1][3], _ab, _b3);                \
        _ab = bcast2(_a0.z);                                                   \
        fma2(acc2[2][0], _ab, _b0); fma2(acc2[2][1], _ab, _b1);                \
        fma2(acc2[2][2], _ab, _b2); fma2(acc2[2][3], _ab, _b3);                \
        _ab = bcast2(_a0.w);                                                   \
        fma2(acc2[3][0], _ab, _b0); fma2(acc2[3][1], _ab, _b1);                \
        fma2(acc2[3][2], _ab, _b2); fma2(acc2[3][3], _ab, _b3);                \
        _ab = bcast2(_a1.x);                                                   \
        fma2(acc2[4][0], _ab, _b0); fma2(acc2[4][1], _ab, _b1);                \
        fma2(acc2[4][2], _ab, _b2); fma2(acc2[4][3], _ab, _b3);                \
        _ab = bcast2(_a1.y);                                                   \
        fma2(acc2[5][0], _ab, _b0); fma2(acc2[5][1], _ab, _b1);                \
        fma2(acc2[5][2], _ab, _b2); fma2(acc2[5][3], _ab, _b3);                \
        _ab = bcast2(_a1.z);                                                   \
        fma2(acc2[6][0], _ab, _b0); fma2(acc2[6][1], _ab, _b1);                \
        fma2(acc2[6][2], _ab, _b2); fma2(acc2[6][3], _ab, _b3);                \
        _ab = bcast2(_a1.w);                                                   \
        fma2(acc2[7][0], _ab, _b0); fma2(acc2[7][1], _ab, _b1);                \
        fma2(acc2[7][2], _ab, _b2); fma2(acc2[7][3], _ab, _b3);                \
    } while (0)

// ---------------------------------------------------------------------------
// 2) h2 = h @ Wn + bn    [FFMA2 SIMT, proven]
// ---------------------------------------------------------------------------
__global__ __launch_bounds__(256) void node_gemm_kernel(
    const float* __restrict__ A,
    const float* __restrict__ B,
    const float* __restrict__ bias)
{
    const int BM = 128, BK = 8;
    const int M = NN, N = DIN, K = DIN;
    __shared__ float As[2][BK][BM];
    __shared__ float Bs[2][BK][128];

    int tid  = threadIdx.x;
    int aRow = tid >> 1;
    int aCol = (tid & 1) << 2;
    int bRow = tid >> 5;
    int bCol = (tid & 31) << 2;
    int rowBase = blockIdx.y * BM;
    int colBase = blockIdx.x * 128;
    int ty = tid >> 4, tx = tid & 15;
    int gr = rowBase + aRow;
    bool aOk = (gr < M);

    unsigned long long acc2[8][4];
#pragma unroll
    for (int i = 0; i < 8; i++)
#pragma unroll
        for (int j = 0; j < 4; j++) acc2[i][j] = 0ull;

    float4 av = make_float4(0.f, 0.f, 0.f, 0.f);
    if (aOk) av = *reinterpret_cast<const float4*>(A + (size_t)gr * K + aCol);
    float4 bv = *reinterpret_cast<const float4*>(B + (size_t)bRow * N + colBase + bCol);
    As[0][aCol + 0][aRow] = av.x;
    As[0][aCol + 1][aRow] = av.y;
    As[0][aCol + 2][aRow] = av.z;
    As[0][aCol + 3][aRow] = av.w;
    *reinterpret_cast<float4*>(&Bs[0][bRow][bCol]) = bv;
    __syncthreads();

    int buf = 0;
    for (int kt = 0; kt < K; kt += BK) {
        bool hasNext = (kt + BK < K);
        if (hasNext) {
            av = make_float4(0.f, 0.f, 0.f, 0.f);
            if (aOk) av = *reinterpret_cast<const float4*>(A + (size_t)gr * K + kt + BK + aCol);
            bv = *reinterpret_cast<const float4*>(B + (size_t)(kt + BK + bRow) * N + colBase + bCol);
        }
#pragma unroll
        for (int k = 0; k < BK; k++)
            MICRO_K_STEP(&As[buf][k][ty * 8], &Bs[buf][k][tx * 8]);
        if (hasNext) {
            int nb = buf ^ 1;
            As[nb][aCol + 0][aRow] = av.x;
            As[nb][aCol + 1][aRow] = av.y;
            As[nb][aCol + 2][aRow] = av.z;
            As[nb][aCol + 3][aRow] = av.w;
            *reinterpret_cast<float4*>(&Bs[nb][bRow][bCol]) = bv;
            __syncthreads();
            buf = nb;
        }
    }

#pragma unroll
    for (int i = 0; i < 8; i++) {
        int r = rowBase + ty * 8 + i;
        if (r >= M) continue;
#pragma unroll
        for (int jp = 0; jp < 4; jp += 2) {
            int c = colBase + tx * 8 + jp * 2;
            float4 o;
            o.x = lo2(acc2[i][jp + 0]) + bias[c + 0];
            o.y = hi2(acc2[i][jp + 0]) + bias[c + 1];
            o.z = lo2(acc2[i][jp + 1]) + bias[c + 2];
            o.w = hi2(acc2[i][jp + 1]) + bias[c + 3];
            *reinterpret_cast<float4*>(g_h2 + (size_t)r * N + c) = o;
        }
    }
}

// ---------------------------------------------------------------------------
// 3) z1 src-side scatter
// ---------------------------------------------------------------------------
__global__ __launch_bounds__(256) void edge_src_kernel(
    const float* __restrict__ natt,
    const int* __restrict__ src,
    const int* __restrict__ dst)
{
    int e    = blockIdx.x * 4 + (threadIdx.x >> 6);
    int lane = threadIdx.x & 63;
    if (e >= NE) return;
    int s = __ldg(&src[e]);
    int d = __ldg(&dst[e]);
    float a = __ldg(&natt[s]);
    float4 v = *reinterpret_cast<const float4*>(g_h2 + (size_t)s * DIN + lane * 4);
    float* p = g_hsum + (size_t)d * DSUM + lane * 4;
    red_add_v4(p, a * v.x, a * v.y, a * v.z, a * v.w);
}

// ---------------------------------------------------------------------------
// 4) z1 dst-side (deg-weighted, non-atomic)
// ---------------------------------------------------------------------------
__global__ __launch_bounds__(64) void node_term_kernel(const float* __restrict__ natt) {
    int n    = blockIdx.x;
    int lane = threadIdx.x;
    float c = (float)g_deg[n] * __ldg(&natt[n]);
    float4 v = *reinterpret_cast<const float4*>(g_h2 + (size_t)n * DIN + lane * 4);
    float* p = g_hsum + (size_t)n * DSUM + lane * 4;
    float4 o = *reinterpret_cast<float4*>(p);
    o.x += c * v.x; o.y += c * v.y; o.z += c * v.z; o.w += c * v.w;
    *reinterpret_cast<float4*>(p) = o;
}

// ---------------------------------------------------------------------------
// Common mma.sync tile config (shared by kernels 5 and 6)
// CTA 128x128, 8 warps (2 M x 4 N), warp tile 64x32 (4x4 m16n8k16 frags).
// SMEM tiles padded to 40 bf16/row; double-buffered.
// ---------------------------------------------------------------------------
#define FPAD 40                          // padded row length (bf16 elems)
#define TILE_BYTES (128 * FPAD * 2)      // 10240
#define BUF_BYTES  (4 * TILE_BYTES)      // AHI, ALO, BHI, BLO = 40960
#define MMA_SMEM   (2 * BUF_BYTES)       // 81920

// ---------------------------------------------------------------------------
// 5) z2 = eatt * (rel @ Wr + br) scattered into h_sum[dst, 256:384]
//    via mma.sync bf16-split. 128 edges x 128 cols per CTA; K=128 (4 chunks).
// ---------------------------------------------------------------------------
__global__ __launch_bounds__(256, 1) void rel_gemm_mma_scatter_kernel(
    const float* __restrict__ A,      // rel [NE, DREL]
    const float* __restrict__ bias,   // br [DREL]
    const float* __restrict__ eatt,   // [NE]
    const int* __restrict__ dst)      // [NE]
{
    extern __shared__ char smem[];
    int tid  = threadIdx.x;
    int wid  = tid >> 5;
    int lane = tid & 31;
    int wm = wid & 1;
    int wn = wid >> 1;
    int g  = lane >> 2;
    int c2 = (lane & 3) * 2;
    int rowBase = blockIdx.x * 128;   // edge tile (NE % 128 == 0, always in bounds)

    auto AHI = [&](int b) { return smem + b * BUF_BYTES; };
    auto ALO = [&](int b) { return smem + b * BUF_BYTES + TILE_BYTES; };
    auto BHI = [&](int b) { return smem + b * BUF_BYTES + 2 * TILE_BYTES; };
    auto BLO = [&](int b) { return smem + b * BUF_BYTES + 3 * TILE_BYTES; };

    float acc[4][4][4];
#pragma unroll
    for (int i = 0; i < 4; i++)
#pragma unroll
        for (int j = 0; j < 4; j++)
#pragma unroll
            for (int r = 0; r < 4; r++) acc[i][j][r] = 0.f;

    float4 pa[4];
    uint4  pbh[2], pbl[2];

    auto loadA = [&](int kt, int it) -> float4 {
        int idx = tid + it * 256;
        int row = idx >> 3, cu = idx & 7;           // cu in [0,8): 8 x 4 floats = 32 k
        return *reinterpret_cast<const float4*>(A + (size_t)(rowBase + row) * DREL + kt + cu * 4);
    };
    auto loadB = [&](const __nv_bfloat16* W, int kt, int it) -> uint4 {
        int idx = tid + it * 256;
        int row = idx >> 2, unit = idx & 3;         // unit in [0,4): 4 x 8 bf16 = 32 k
        return *reinterpret_cast<const uint4*>(W + (size_t)row * DREL + kt + unit * 8);
    };
    auto storeChunk = [&](int b) {
#pragma unroll
        for (int it = 0; it < 4; it++) {
            int idx = tid + it * 256;
            int row = idx >> 3, cu = idx & 7;
            __nv_bfloat16 h0, l0, h1, l1, h2v, l2v, h3, l3;
            split_bf16(pa[it].x, h0, l0); split_bf16(pa[it].y, h1, l1);
            split_bf16(pa[it].z, h2v, l2v); split_bf16(pa[it].w, h3, l3);
            unsigned* dh = reinterpret_cast<unsigned*>(AHI(b) + row * (FPAD * 2) + cu * 8);
            unsigned* dl = reinterpret_cast<unsigned*>(ALO(b) + row * (FPAD * 2) + cu * 8);
            dh[0] = pack_bf16x2(h0, h1); dh[1] = pack_bf16x2(h2v, h3);
            dl[0] = pack_bf16x2(l0, l1); dl[1] = pack_bf16x2(l2v, l3);
        }
#pragma unroll
        for (int it = 0; it < 2; it++) {
            int idx = tid + it * 256;
            int row = idx >> 2, unit = idx & 3;
            *reinterpret_cast<uint4*>(BHI(b) + row * (FPAD * 2) + unit * 16) = pbh[it];
            *reinterpret_cast<uint4*>(BLO(b) + row * (FPAD * 2) + unit * 16) = pbl[it];
        }
    };

    int aBase[4], bBase[4];
#pragma unroll
    for (int mt = 0; mt < 4; mt++)
        aBase[mt] = (wm * 64 + mt * 16 + g) * (FPAD * 2) + c2 * 2;
#pragma unroll
    for (int nt = 0; nt < 4; nt++)
        bBase[nt] = (wn * 32 + nt * 8 + g) * (FPAD * 2) + c2 * 2;

    // prologue
#pragma unroll
    for (int it = 0; it < 4; it++) pa[it] = loadA(0, it);
#pragma unroll
    for (int it = 0; it < 2; it++) { pbh[it] = loadB(g_wr_hi, 0, it); pbl[it] = loadB(g_wr_lo, 0, it); }
    storeChunk(0);
    __syncthreads();

    int buf = 0;
    for (int kt = 0; kt < DREL; kt += 32) {
        bool hasNext = (kt + 32 < DREL);
        if (hasNext) {
#pragma unroll
            for (int it = 0; it < 4; it++) pa[it] = loadA(kt + 32, it);
#pragma unroll
            for (int it = 0; it < 2; it++) {
                pbh[it] = loadB(g_wr_hi, kt + 32, it);
                pbl[it] = loadB(g_wr_lo, kt + 32, it);
            }
        }
        const char* ah = AHI(buf); const char* al = ALO(buf);
        const char* bh = BHI(buf); const char* bl = BLO(buf);
#pragma unroll
        for (int kk = 0; kk < 32; kk += 16) {
            unsigned afh[4][4], afl[4][4], bfh[4][2], bfl[4][2];
#pragma unroll
            for (int mt = 0; mt < 4; mt++) {
                int o = aBase[mt] + kk * 2;
                afh[mt][0] = *reinterpret_cast<const unsigned*>(ah + o);
                afh[mt][1] = *reinterpret_cast<const unsigned*>(ah + o + 8 * FPAD * 2);
                afh[mt][2] = *reinterpret_cast<const unsigned*>(ah + o + 16);
                afh[mt][3] = *reinterpret_cast<const unsigned*>(ah + o + 8 * FPAD * 2 + 16);
                afl[mt][0] = *reinterpret_cast<const unsigned*>(al + o);
                afl[mt][1] = *reinterpret_cast<const unsigned*>(al + o + 8 * FPAD * 2);
                afl[mt][2] = *reinterpret_cast<const unsigned*>(al + o + 16);
                afl[mt][3] = *reinterpret_cast<const unsigned*>(al + o + 8 * FPAD * 2 + 16);
            }
#pragma unroll
            for (int nt = 0; nt < 4; nt++) {
                int o = bBase[nt] + kk * 2;
                bfh[nt][0] = *reinterpret_cast<const unsigned*>(bh + o);
                bfh[nt][1] = *reinterpret_cast<const unsigned*>(bh + o + 16);
                bfl[nt][0] = *reinterpret_cast<const unsigned*>(bl + o);
                bfl[nt][1] = *reinterpret_cast<const unsigned*>(bl + o + 16);
            }
#pragma unroll
            for (int mt = 0; mt < 4; mt++)
#pragma unroll
                for (int nt = 0; nt < 4; nt++) {
                    mma_bf16(acc[mt][nt], afh[mt], bfh[nt]);
                    mma_bf16(acc[mt][nt], afh[mt], bfl[nt]);
                    mma_bf16(acc[mt][nt], afl[mt], bfh[nt]);
                }
        }
        if (hasNext) {
            int nb = buf ^ 1;
            storeChunk(nb);
            __syncthreads();
            buf = nb;
        }
    }

    // epilogue: z2 = eatt*(acc + br); red.v2 scatter into h_sum[dst, 256+col]
#pragma unroll
    for (int mt = 0; mt < 4; mt++) {
        int r0 = rowBase + wm * 64 + mt * 16 + g;
        int r1 = r0 + 8;
        float s0 = __ldg(&eatt[r0]);
        float s1 = __ldg(&eatt[r1]);
        int   d0 = __ldg(&dst[r0]);
        int   d1 = __ldg(&dst[r1]);
#pragma unroll
        for (int nt = 0; nt < 4; nt++) {
            int col = wn * 32 + nt * 8 + c2;       // 0..127
            float b0 = __ldg(&bias[col]), b1 = __ldg(&bias[col + 1]);
            red_add_v2(g_hsum + (size_t)d0 * DSUM + DIN + col,
                       s0 * (acc[mt][nt][0] + b0), s0 * (acc[mt][nt][1] + b1));
            red_add_v2(g_hsum + (size_t)d1 * DSUM + DIN + col,
                       s1 * (acc[mt][nt][2] + b0), s1 * (acc[mt][nt][3] + b1));
        }
    }
}

// ---------------------------------------------------------------------------
// 6) out = relu([h2 | h_sum] @ Wa + ba) via mma.sync bf16-split (R7, audited)
// ---------------------------------------------------------------------------
__global__ __launch_bounds__(256, 1) void final_gemm_mma_kernel(
    const float* __restrict__ bias,   // ba [DOUT]
    float* __restrict__ C)            // out [NN, DOUT]
{
    extern __shared__ char smem[];
    int tid  = threadIdx.x;
    int wid  = tid >> 5;
    int lane = tid & 31;
    int wm = wid & 1;
    int wn = wid >> 1;
    int g  = lane >> 2;
    int c2 = (lane & 3) * 2;
    int rowBase = blockIdx.y * 128;
    int colBase = blockIdx.x * 128;

    auto AHI = [&](int b) { return smem + b * BUF_BYTES; };
    auto ALO = [&](int b) { return smem + b * BUF_BYTES + TILE_BYTES; };
    auto BHI = [&](int b) { return smem + b * BUF_BYTES + 2 * TILE_BYTES; };
    auto BLO = [&](int b) { return smem + b * BUF_BYTES + 3 * TILE_BYTES; };

    float acc[4][4][4];
#pragma unroll
    for (int i = 0; i < 4; i++)
#pragma unroll
        for (int j = 0; j < 4; j++)
#pragma unroll
            for (int r = 0; r < 4; r++) acc[i][j][r] = 0.f;

    float4 pa[4];
    uint4  pbh[2], pbl[2];

    auto loadA = [&](int kt, int it) -> float4 {
        int idx = tid + it * 256;
        int row = idx >> 3, cu = idx & 7;
        int gr = rowBase + row;
        if (gr >= NN) return make_float4(0.f, 0.f, 0.f, 0.f);
        const float* sp = (kt < DIN)
            ? (g_h2   + (size_t)gr * DIN  + kt + cu * 4)
            : (g_hsum + (size_t)gr * DSUM + (kt - DIN) + cu * 4);
        return *reinterpret_cast<const float4*>(sp);
    };
    auto loadB = [&](const __nv_bfloat16* W, int kt, int it) -> uint4 {
        int idx = tid + it * 256;
        int row = idx >> 2, unit = idx & 3;
        return *reinterpret_cast<const uint4*>(W + (size_t)(colBase + row) * DCAT + kt + unit * 8);
    };
    auto storeChunk = [&](int b) {
#pragma unroll
        for (int it = 0; it < 4; it++) {
            int idx = tid + it * 256;
            int row = idx >> 3, cu = idx & 7;
            __nv_bfloat16 h0, l0, h1, l1, h2v, l2v, h3, l3;
            split_bf16(pa[it].x, h0, l0); split_bf16(pa[it].y, h1, l1);
            split_bf16(pa[it].z, h2v, l2v); split_bf16(pa[it].w, h3, l3);
            unsigned* dh = reinterpret_cast<unsigned*>(AHI(b) + row * (FPAD * 2) + cu * 8);
            unsigned* dl = reinterpret_cast<unsigned*>(ALO(b) + row * (FPAD * 2) + cu * 8);
            dh[0] = pack_bf16x2(h0, h1); dh[1] = pack_bf16x2(h2v, h3);
            dl[0] = pack_bf16x2(l0, l1); dl[1] = pack_bf16x2(l2v, l3);
        }
#pragma unroll
        for (int it = 0; it < 2; it++) {
            int idx = tid + it * 256;
            int row = idx >> 2, unit = idx & 3;
            *reinterpret_cast<uint4*>(BHI(b) + row * (FPAD * 2) + unit * 16) = pbh[it];
            *reinterpret_cast<uint4*>(BLO(b) + row * (FPAD * 2) + unit * 16) = pbl[it];
        }
    };

    int aBase[4], bBase[4];
#pragma unroll
    for (int mt = 0; mt < 4; mt++)
        aBase[mt] = (wm * 64 + mt * 16 + g) * (FPAD * 2) + c2 * 2;
#pragma unroll
    for (int nt = 0; nt < 4; nt++)
        bBase[nt] = (wn * 32 + nt * 8 + g) * (FPAD * 2) + c2 * 2;

    // prologue: chunk 0
#pragma unroll
    for (int it = 0; it < 4; it++) pa[it] = loadA(0, it);
#pragma unroll
    for (int it = 0; it < 2; it++) { pbh[it] = loadB(g_wt_hi, 0, it); pbl[it] = loadB(g_wt_lo, 0, it); }
    storeChunk(0);
    __syncthreads();

    int buf = 0;
    for (int kt = 0; kt < DCAT; kt += 32) {
        bool hasNext = (kt + 32 < DCAT);
        if (hasNext) {
#pragma unroll
            for (int it = 0; it < 4; it++) pa[it] = loadA(kt + 32, it);
#pragma unroll
            for (int it = 0; it < 2; it++) {
                pbh[it] = loadB(g_wt_hi, kt + 32, it);
                pbl[it] = loadB(g_wt_lo, kt + 32, it);
            }
        }
        const char* ah = AHI(buf); const char* al = ALO(buf);
        const char* bh = BHI(buf); const char* bl = BLO(buf);
#pragma unroll
        for (int kk = 0; kk < 32; kk += 16) {
            unsigned afh[4][4], afl[4][4], bfh[4][2], bfl[4][2];
#pragma unroll
            for (int mt = 0; mt < 4; mt++) {
                int o = aBase[mt] + kk * 2;
                afh[mt][0] = *reinterpret_cast<const unsigned*>(ah + o);
                afh[mt][1] = *reinterpret_cast<const unsigned*>(ah + o + 8 * FPAD * 2);
                afh[mt][2] = *reinterpret_cast<const unsigned*>(ah + o + 16);
                afh[mt][3] = *reinterpret_cast<const unsigned*>(ah + o + 8 * FPAD * 2 + 16);
                afl[mt][0] = *reinterpret_cast<const unsigned*>(al + o);
                afl[mt][1] = *reinterpret_cast<const unsigned*>(al + o + 8 * FPAD * 2);
                afl[mt][2] = *reinterpret_cast<const unsigned*>(al + o + 16);
                afl[mt][3] = *reinterpret_cast<const unsigned*>(al + o + 8 * FPAD * 2 + 16);
            }
#pragma unroll
            for (int nt = 0; nt < 4; nt++) {
                int o = bBase[nt] + kk * 2;
                bfh[nt][0] = *reinterpret_cast<const unsigned*>(bh + o);
                bfh[nt][1] = *reinterpret_cast<const unsigned*>(bh + o + 16);
                bfl[nt][0] = *reinterpret_cast<const unsigned*>(bl + o);
                bfl[nt][1] = *reinterpret_cast<const unsigned*>(bl + o + 16);
            }
#pragma unroll
            for (int mt = 0; mt < 4; mt++)
#pragma unroll
                for (int nt = 0; nt < 4; nt++) {
                    mma_bf16(acc[mt][nt], afh[mt], bfh[nt]);
                    mma_bf16(acc[mt][nt], afh[mt], bfl[nt]);
                    mma_bf16(acc[mt][nt], afl[mt], bfh[nt]);
                }
        }
        if (hasNext) {
            int nb = buf ^ 1;
            storeChunk(nb);
            __syncthreads();
            buf = nb;
        }
    }

    // epilogue: bias + relu + store
#pragma unroll
    for (int mt = 0; mt < 4; mt++) {
        int r0 = rowBase + wm * 64 + mt * 16 + g;
        int r1 = r0 + 8;
#pragma unroll
        for (int nt = 0; nt < 4; nt++) {
            int col = colBase + wn * 32 + nt * 8 + c2;
            float b0 = __ldg(&bias[col]), b1 = __ldg(&bias[col + 1]);
            if (r0 < NN) {
                float2 v;
                v.x = fmaxf(acc[mt][nt][0] + b0, 0.f);
                v.y = fmaxf(acc[mt][nt][1] + b1, 0.f);
                *reinterpret_cast<float2*>(C + (size_t)r0 * DOUT + col) = v;
            }
            if (r1 < NN) {
                float2 v;
                v.x = fmaxf(acc[mt][nt][2] + b0, 0.f);
                v.y = fmaxf(acc[mt][nt][3] + b1, 0.f);
                *reinterpret_cast<float2*>(C + (size_t)r1 * DOUT + col) = v;
            }
        }
    }
}

// ---------------------------------------------------------------------------
extern "C" void kernel_launch(void* const* d_in, const int* in_sizes, int n_in,
                              void* d_out, int out_size) {
    const float* h    = (const float*)d_in[0];
    const float* natt = (const float*)d_in[1];
    const float* rel  = (const float*)d_in[2];
    const float* eatt = (const float*)d_in[3];
    const float* Wn   = (const float*)d_in[4];
    const float* bn   = (const float*)d_in[5];
    const float* Wr   = (const float*)d_in[6];
    const float* br   = (const float*)d_in[7];
    const float* Wa   = (const float*)d_in[8];
    const float* ba   = (const float*)d_in[9];
    const int*   src  = (const int*)d_in[10];
    const int*   dst  = (const int*)d_in[11];
    float* out = (float*)d_out;
    (void)in_sizes; (void)n_in; (void)out_size;

    cudaFuncSetAttribute(final_gemm_mma_kernel,
                         cudaFuncAttributeMaxDynamicSharedMemorySize, MMA_SMEM);
    cudaFuncSetAttribute(rel_gemm_mma_scatter_kernel,
                         cudaFuncAttributeMaxDynamicSharedMemorySize, MMA_SMEM);

    // 0) zero scratch
    zero_kernel<<<(NN * DSUM / 4 + 255) / 256, 256>>>();
    // 1) in-degree histogram + weight prep
    deg_kernel<<<(NE + 255) / 256, 256>>>(dst);
    prep_w_kernel<<<(DOUT * DCAT + 255) / 256, 256>>>(Wa);
    prep_wr_kernel<<<(DREL * DREL + 255) / 256, 256>>>(Wr);
    // 2) h2 = h@Wn + bn
    {
        dim3 g(DIN / 128, (NN + 127) / 128);
        node_gemm_kernel<<<g, 256>>>(h, Wn, bn);
    }
    // 3) src-side message scatter
    edge_src_kernel<<<NE / 4, 256>>>(natt, src, dst);
    // 4) dst-side term
    node_term_kernel<<<NN, 64>>>(natt);
    // 5) rel GEMM + scatter via mma.sync
    rel_gemm_mma_scatter_kernel<<<NE / 128, 256, MMA_SMEM>>>(rel, br, eatt, dst);
    // 6) final GEMM + bias + relu via mma.sync
    {
        dim3 g(DOUT / 128, (NN + 127) / 128);
        final_gemm_mma_kernel<<<g, 256, MMA_SMEM>>>(ba, out);
    }
}